// round 1
// baseline (speedup 1.0000x reference)
#include <cuda_runtime.h>
#include <math.h>

// Problem constants (fixed for NMT_17652315587342)
#define BB 64
#define SS 2048
#define HH 1024
#define DD 64
#define G4H (4*HH)

// ---------------- scratch (__device__ globals; no allocation allowed) ----------
__device__ float g_gates[BB * G4H];      // [64, 4096]
__device__ float g_yt[BB * HH];          // [64, 1024]
__device__ float g_part2[4 * BB * HH];   // split-K partials for yt @ W_ht2tan^T
__device__ float g_part3[4 * BB * HH];   // split-K partials for ct @ W_ct2ht^T
__device__ float g_ct[BB * HH];          // [64, 1024]
__device__ float g_p[BB];
__device__ int   g_left[BB];
__device__ int   g_right[BB];

__device__ __forceinline__ float sigmoidf_(float x) { return 1.0f / (1.0f + expf(-x)); }

// ---------------------------------------------------------------------------
// Skinny GEMM: C[64, N] = A[64, K] @ W[N, K]^T (+bias), with optional second
// (A2,W2) pair concatenated along K, and split-K via blockIdx.y writing to a
// per-chunk partial slab (C + by*64*N). BM=64, BN=32, BK=32, 128 threads,
// 4x4 register micro-tile (float4 LDS on both operands -> 2 LDS / 16 FFMA).
// ---------------------------------------------------------------------------
#define BM 64
#define BN 32
#define BKT 32
#define AST 68   // 272B row: 16B-aligned for float4, (4k+m)%32 banking
#define WST 36   // 144B row: 16B-aligned

__global__ __launch_bounds__(128) void gemm_at(
    const float* __restrict__ A1, const float* __restrict__ W1, int K1,
    const float* __restrict__ A2, const float* __restrict__ W2, int K2,
    const float* __restrict__ bias1, const float* __restrict__ bias2,
    float* __restrict__ C, int N, int kchunk)
{
    __shared__ float As[BKT][AST];
    __shared__ float Ws[BKT][WST];

    const int tid = threadIdx.x;
    const int tx = tid & 7;    // n micro: n = n0 + tx*4 + j
    const int ty = tid >> 3;   // m micro: m = ty*4 + i
    const int n0 = blockIdx.x * BN;
    const int kstart = blockIdx.y * kchunk;
    const int lk = tid & 31;   // k lane for tile loads (coalesced along K)
    const int lr = tid >> 5;   // 0..3

    float acc[4][4] = {};

    for (int k0 = kstart; k0 < kstart + kchunk; k0 += BKT) {
        const float* A; const float* W; int K, kk;
        if (k0 < K1) { A = A1; W = W1; K = K1; kk = k0; }
        else         { A = A2; W = W2; K = K2; kk = k0 - K1; }

        // A tile: 64 rows x 32 k, read 32 consecutive k per row (128B/warp row)
        #pragma unroll
        for (int i = 0; i < 16; i++) {
            int m = lr + 4 * i;
            As[lk][m] = A[(size_t)m * K + kk + lk];
        }
        // W tile: 32 rows x 32 k
        #pragma unroll
        for (int i = 0; i < 8; i++) {
            int n = lr + 4 * i;
            Ws[lk][n] = W[(size_t)(n0 + n) * K + kk + lk];
        }
        __syncthreads();

        #pragma unroll
        for (int k = 0; k < BKT; k++) {
            float4 a = *(const float4*)&As[k][ty << 2];
            float4 b = *(const float4*)&Ws[k][tx << 2];
            acc[0][0] += a.x * b.x; acc[0][1] += a.x * b.y; acc[0][2] += a.x * b.z; acc[0][3] += a.x * b.w;
            acc[1][0] += a.y * b.x; acc[1][1] += a.y * b.y; acc[1][2] += a.y * b.z; acc[1][3] += a.y * b.w;
            acc[2][0] += a.z * b.x; acc[2][1] += a.z * b.y; acc[2][2] += a.z * b.z; acc[2][3] += a.z * b.w;
            acc[3][0] += a.w * b.x; acc[3][1] += a.w * b.y; acc[3][2] += a.w * b.z; acc[3][3] += a.w * b.w;
        }
        __syncthreads();
    }

    float badd[4] = {0.f, 0.f, 0.f, 0.f};
    if (bias1) {
        #pragma unroll
        for (int j = 0; j < 4; j++) badd[j] = bias1[n0 + (tx << 2) + j];
    }
    if (bias2) {
        #pragma unroll
        for (int j = 0; j < 4; j++) badd[j] += bias2[n0 + (tx << 2) + j];
    }

    float* Co = C + (size_t)blockIdx.y * BM * N;
    #pragma unroll
    for (int i = 0; i < 4; i++) {
        int m = (ty << 2) + i;
        float4 o;
        o.x = acc[i][0] + badd[0];
        o.y = acc[i][1] + badd[1];
        o.z = acc[i][2] + badd[2];
        o.w = acc[i][3] + badd[3];
        *(float4*)&Co[(size_t)m * N + n0 + (tx << 2)] = o;
    }
}

// ---------------- LSTM cell elementwise (gate order i,f,g,o) -----------------
__global__ void lstm_kernel(const float* __restrict__ c0)
{
    int idx = blockIdx.x * blockDim.x + threadIdx.x;   // 64*1024
    int b = idx >> 10;
    int h = idx & 1023;
    const float* gr = g_gates + (size_t)b * G4H;
    float gi = gr[h];
    float gf = gr[HH + h];
    float gg = gr[2 * HH + h];
    float go = gr[3 * HH + h];
    float c = sigmoidf_(gf) * c0[idx] + sigmoidf_(gi) * tanhf(gg);
    g_yt[idx] = sigmoidf_(go) * tanhf(c);
}

// ---------------- p_t = len * sigmoid(tanh(yt W1^T) w2) ---------------------
__global__ __launch_bounds__(256) void pt_kernel(const float* __restrict__ Wt2p,
                                                 const int* __restrict__ elen)
{
    int b = blockIdx.x;
    __shared__ float sd[256];
    float s = 0.f;
    for (int h = threadIdx.x; h < HH; h += 256) {
        float v = g_part2[(size_t)b * HH + h]
                + g_part2[(size_t)BB * HH + (size_t)b * HH + h]
                + g_part2[(size_t)2 * BB * HH + (size_t)b * HH + h]
                + g_part2[(size_t)3 * BB * HH + (size_t)b * HH + h];
        s += tanhf(v) * Wt2p[h];
    }
    sd[threadIdx.x] = s;
    __syncthreads();
    for (int st = 128; st > 0; st >>= 1) {
        if (threadIdx.x < st) sd[threadIdx.x] += sd[threadIdx.x + st];
        __syncthreads();
    }
    if (threadIdx.x == 0) {
        float pt = sigmoidf_(sd[0]);
        int len = elen[b];
        float p = (float)len * pt;
        int pf = (int)floorf(p);
        g_p[b] = p;
        g_left[b]  = max(0, pf - DD);
        g_right[b] = min(len, pf + DD);
    }
}

// ---------------- windowed attention: scores, softmax*gauss, context --------
// One block per batch element. Window width <= 2*D = 128.
__global__ __launch_bounds__(1024) void attn_kernel(const float* __restrict__ enc)
{
    int b = blockIdx.x;
    int tid = threadIdx.x;
    __shared__ float yts[HH];
    __shared__ float sc[2 * DD];
    __shared__ float ats[2 * DD];
    __shared__ float s_max, s_sum;

    yts[tid] = g_yt[(size_t)b * HH + tid];
    int left = g_left[b], right = g_right[b];
    float p = g_p[b];
    int width = right - left;
    __syncthreads();

    int w = tid >> 5, lane = tid & 31;
    const float* encb = enc + ((size_t)b * SS + left) * HH;

    // scores: one warp per window position
    for (int j = w; j < width; j += 32) {
        const float* er = encb + (size_t)j * HH;
        float a = 0.f;
        #pragma unroll 8
        for (int h = lane; h < HH; h += 32) a += yts[h] * er[h];
        #pragma unroll
        for (int off = 16; off > 0; off >>= 1) a += __shfl_down_sync(0xffffffffu, a, off);
        if (lane == 0) sc[j] = a;
    }
    __syncthreads();

    // softmax stats over the window (warp 0)
    if (w == 0) {
        float m = -3.0e38f;
        for (int j = lane; j < width; j += 32) m = fmaxf(m, sc[j]);
        #pragma unroll
        for (int off = 16; off > 0; off >>= 1) m = fmaxf(m, __shfl_xor_sync(0xffffffffu, m, off));
        float s = 0.f;
        for (int j = lane; j < width; j += 32) s += expf(sc[j] - m);
        #pragma unroll
        for (int off = 16; off > 0; off >>= 1) s += __shfl_xor_sync(0xffffffffu, s, off);
        if (lane == 0) { s_max = m; s_sum = s; }
    }
    __syncthreads();

    // at = softmax * gaussian (D*D/2 = 2048)
    if (tid < width) {
        float d = (float)(left + tid) - p;
        ats[tid] = expf(sc[tid] - s_max) / s_sum * expf(-d * d * (1.0f / 2048.0f));
    }
    __syncthreads();

    // context: ct[h] = sum_j at[j] * enc[b, left+j, h]  (window is L2-resident)
    float acc = 0.f;
    const float* col = encb + tid;
    #pragma unroll 4
    for (int j = 0; j < width; j++) acc += ats[j] * col[(size_t)j * HH];
    g_ct[(size_t)b * HH + tid] = acc;
}

// ---------------- deterministic split-K reduce into d_out -------------------
__global__ void reduce_out(float* __restrict__ out)
{
    int idx = blockIdx.x * blockDim.x + threadIdx.x;   // 64*1024
    out[idx] = g_part3[idx]
             + g_part3[BB * HH + idx]
             + g_part3[2 * BB * HH + idx]
             + g_part3[3 * BB * HH + idx];
}

// ---------------------------------------------------------------------------
extern "C" void kernel_launch(void* const* d_in, const int* in_sizes, int n_in,
                              void* d_out, int out_size)
{
    const float* enc      = (const float*)d_in[0];   // [64, 2048, 1024]
    const float* x_t      = (const float*)d_in[1];   // [64, 2048]
    const float* h0       = (const float*)d_in[2];   // [64, 1024]
    const float* c0       = (const float*)d_in[3];   // [64, 1024]
    const float* W_ih     = (const float*)d_in[4];   // [4096, 2048]
    const float* W_hh     = (const float*)d_in[5];   // [4096, 1024]
    const float* b_ih     = (const float*)d_in[6];   // [4096]
    const float* b_hh     = (const float*)d_in[7];   // [4096]
    const float* W_ht2tan = (const float*)d_in[8];   // [1024, 1024]
    const float* W_tan2pt = (const float*)d_in[9];   // [1, 1024]
    const float* W_ct2ht  = (const float*)d_in[10];  // [1024, 1024]
    const int*   elen     = (const int*)d_in[11];    // [64]
    float* out = (float*)d_out;
    (void)in_sizes; (void)n_in; (void)out_size;

    float *p_gates, *p_yt, *p_part2, *p_part3, *p_ct;
    cudaGetSymbolAddress((void**)&p_gates, g_gates);
    cudaGetSymbolAddress((void**)&p_yt,    g_yt);
    cudaGetSymbolAddress((void**)&p_part2, g_part2);
    cudaGetSymbolAddress((void**)&p_part3, g_part3);
    cudaGetSymbolAddress((void**)&p_ct,    g_ct);

    // 1) gates = [x_t|h0] @ [W_ih|W_hh]^T + b_ih + b_hh   (N=4096, K=3072)
    gemm_at<<<dim3(G4H / BN, 1), 128>>>(x_t, W_ih, 2048, h0, W_hh, 1024,
                                        b_ih, b_hh, p_gates, G4H, 3072);
    // 2) LSTM cell -> yt
    lstm_kernel<<<(BB * HH) / 256, 256>>>(c0);
    // 3) pre-tanh = yt @ W_ht2tan^T  (split-K=4 partials)
    gemm_at<<<dim3(HH / BN, 4), 128>>>(p_yt, W_ht2tan, HH, nullptr, nullptr, 0,
                                       nullptr, nullptr, p_part2, HH, HH / 4);
    // 4) p_t, window bounds
    pt_kernel<<<BB, 256>>>(W_tan2pt, elen);
    // 5) windowed attention -> ct
    attn_kernel<<<BB, 1024>>>(enc);
    // 6) ht = ct @ W_ct2ht^T  (split-K=4 partials)
    gemm_at<<<dim3(HH / BN, 4), 128>>>(p_ct, W_ct2ht, HH, nullptr, nullptr, 0,
                                       nullptr, nullptr, p_part3, HH, HH / 4);
    // 7) reduce partials -> d_out
    reduce_out<<<(BB * HH) / 256, 256>>>(out);
}

// round 4
// speedup vs baseline: 1.8416x; 1.8416x over previous
#include <cuda_runtime.h>
#include <math.h>

// Problem constants (fixed for NMT_17652315587342)
#define BB 64
#define SS 2048
#define HH 1024
#define DD 64
#define G4H (4*HH)

#define SPLITK_G 2
#define SPLITK_S 8

// ---------------- scratch (__device__ globals) ------------------------------
__device__ float g_gpart[SPLITK_G * BB * G4H];   // gates split-K partials
__device__ float g_yt[BB * HH];
__device__ float g_part2[SPLITK_S * BB * HH];    // yt @ W_ht2tan^T partials
__device__ float g_part3[SPLITK_S * BB * HH];    // ct @ W_ct2ht^T partials
__device__ float g_ct[BB * HH];

__device__ __forceinline__ float sigmoidf_(float x) { return 1.0f / (1.0f + expf(-x)); }

// ---------------------------------------------------------------------------
// Double-buffered skinny GEMM: C_slab[by][64, N] = A[64, Kchunk] @ W[N, Kchunk]^T
// over k in [by*kchunk, (by+1)*kchunk). Optional second (A2,W2) concatenated
// along K at K1. BM=64, BN=64, BKT=16, 128 threads, 4x8 register micro-tile.
// b-quads split at n-offsets {tx*4, 32+tx*4} for conflict-free LDS.128.
// Tile strides 68 floats: 16B-aligned, 2-way max STS conflict.
// ---------------------------------------------------------------------------
#define BM 64
#define BN 64
#define BKT 16
#define ASTR 68
#define WSTR 68

__global__ __launch_bounds__(128) void gemm_db(
    const float* __restrict__ A1, const float* __restrict__ W1, int K1,
    const float* __restrict__ A2, const float* __restrict__ W2,
    float* __restrict__ C, int N, int kchunk)
{
    __shared__ float As[2][BKT][ASTR];
    __shared__ float Ws[2][BKT][WSTR];

    const int tid = threadIdx.x;
    const int kq = tid & 15;          // k within tile
    const int mr = tid >> 4;          // 0..7
    const int tx = tid & 7;           // n quads at tx*4 and 32+tx*4
    const int ty = tid >> 3;          // 0..15 -> m = ty*4
    const int n0 = blockIdx.x * BN;
    const int kbase = blockIdx.y * kchunk;
    const int niter = kchunk / BKT;

    float acc[4][8] = {};
    float ra[8], rw[8];

    // ---- load tile k0 into registers ----
    auto load_regs = [&](int k0, float* a, float* w) {
        const float* A; const float* W; int K, kk;
        if (k0 < K1) { A = A1; W = W1; K = K1; kk = k0; }
        else         { A = A2; W = W2; K = HH; kk = k0 - K1; }   // A2 has K=HH
        #pragma unroll
        for (int i = 0; i < 8; i++)
            a[i] = A[(size_t)(mr + 8 * i) * K + kk + kq];
        #pragma unroll
        for (int i = 0; i < 8; i++)
            w[i] = W[(size_t)(n0 + mr + 8 * i) * K + kk + kq];
    };
    auto store_tile = [&](int buf, const float* a, const float* w) {
        #pragma unroll
        for (int i = 0; i < 8; i++) As[buf][kq][mr + 8 * i] = a[i];
        #pragma unroll
        for (int i = 0; i < 8; i++) Ws[buf][kq][mr + 8 * i] = w[i];
    };

    load_regs(kbase, ra, rw);
    store_tile(0, ra, rw);
    __syncthreads();

    int buf = 0;
    for (int it = 0; it < niter; it++) {
        const bool more = (it + 1 < niter);
        float ra2[8], rw2[8];
        if (more) load_regs(kbase + (it + 1) * BKT, ra2, rw2);

        #pragma unroll
        for (int k = 0; k < BKT; k++) {
            float4 a  = *(const float4*)&As[buf][k][ty << 2];
            float4 b0 = *(const float4*)&Ws[buf][k][tx << 2];
            float4 b1 = *(const float4*)&Ws[buf][k][32 + (tx << 2)];
            float av[4] = {a.x, a.y, a.z, a.w};
            #pragma unroll
            for (int i = 0; i < 4; i++) {
                acc[i][0] += av[i] * b0.x; acc[i][1] += av[i] * b0.y;
                acc[i][2] += av[i] * b0.z; acc[i][3] += av[i] * b0.w;
                acc[i][4] += av[i] * b1.x; acc[i][5] += av[i] * b1.y;
                acc[i][6] += av[i] * b1.z; acc[i][7] += av[i] * b1.w;
            }
        }

        if (more) {
            store_tile(buf ^ 1, ra2, rw2);
            __syncthreads();
        }
        buf ^= 1;
    }

    float* Co = C + (size_t)blockIdx.y * BM * N;
    #pragma unroll
    for (int i = 0; i < 4; i++) {
        int m = (ty << 2) + i;
        float4 o0 = {acc[i][0], acc[i][1], acc[i][2], acc[i][3]};
        float4 o1 = {acc[i][4], acc[i][5], acc[i][6], acc[i][7]};
        *(float4*)&Co[(size_t)m * N + n0 + (tx << 2)]      = o0;
        *(float4*)&Co[(size_t)m * N + n0 + 32 + (tx << 2)] = o1;
    }
}

// ---------------- gates reduce + bias + LSTM cell (order i,f,g,o) -----------
__global__ void lstm_fuse(const float* __restrict__ c0,
                          const float* __restrict__ b_ih,
                          const float* __restrict__ b_hh)
{
    int idx = blockIdx.x * blockDim.x + threadIdx.x;   // 64*1024
    int b = idx >> 10;
    int h = idx & 1023;
    const size_t base = (size_t)b * G4H;
    const size_t slab = (size_t)BB * G4H;
    float gv[4];
    #pragma unroll
    for (int g = 0; g < 4; g++) {
        int gh = g * HH + h;
        gv[g] = g_gpart[base + gh] + g_gpart[slab + base + gh]
              + b_ih[gh] + b_hh[gh];
    }
    float c = sigmoidf_(gv[1]) * c0[idx] + sigmoidf_(gv[0]) * tanhf(gv[2]);
    g_yt[idx] = sigmoidf_(gv[3]) * tanhf(c);
}

// ---------------- fused p_t + windowed attention ----------------------------
// One block per batch element, 1024 threads.
__global__ __launch_bounds__(1024) void attn_pt_kernel(
    const float* __restrict__ enc, const float* __restrict__ Wt2p,
    const int* __restrict__ elen)
{
    int b = blockIdx.x;
    int tid = threadIdx.x;
    int w = tid >> 5, lane = tid & 31;

    __shared__ __align__(16) float yts[HH];
    __shared__ float sc[2 * DD];
    __shared__ float ats[2 * DD];
    __shared__ float sred[32];
    __shared__ float s_p, s_max, s_sum;
    __shared__ int s_left, s_right;

    // ---- p_t: reduce part2 over split-K, tanh, dot with Wt2p ----
    {
        float v = 0.f;
        #pragma unroll
        for (int s = 0; s < SPLITK_S; s++)
            v += g_part2[(size_t)s * BB * HH + (size_t)b * HH + tid];
        float sv = tanhf(v) * Wt2p[tid];
        #pragma unroll
        for (int off = 16; off > 0; off >>= 1)
            sv += __shfl_down_sync(0xffffffffu, sv, off);
        if (lane == 0) sred[w] = sv;
    }
    yts[tid] = g_yt[(size_t)b * HH + tid];
    __syncthreads();
    if (w == 0) {
        float sv = sred[lane];
        #pragma unroll
        for (int off = 16; off > 0; off >>= 1)
            sv += __shfl_down_sync(0xffffffffu, sv, off);
        if (lane == 0) {
            float pt = sigmoidf_(sv);
            int len = elen[b];
            float p = (float)len * pt;
            int pf = (int)floorf(p);
            s_p = p;
            s_left = max(0, pf - DD);
            s_right = min(len, pf + DD);
        }
    }
    __syncthreads();

    const int left = s_left, right = s_right;
    const float p = s_p;
    const int width = right - left;
    const float* encb = enc + ((size_t)b * SS + left) * HH;

    // ---- scores: one warp per window position, float4 loads ----
    for (int j = w; j < width; j += 32) {
        const float4* er = (const float4*)(encb + (size_t)j * HH);
        const float4* yv = (const float4*)yts;
        float a = 0.f;
        #pragma unroll 4
        for (int h4 = lane; h4 < HH / 4; h4 += 32) {
            float4 e = er[h4];
            float4 y = yv[h4];
            a += e.x * y.x + e.y * y.y + e.z * y.z + e.w * y.w;
        }
        #pragma unroll
        for (int off = 16; off > 0; off >>= 1)
            a += __shfl_down_sync(0xffffffffu, a, off);
        if (lane == 0) sc[j] = a;
    }
    __syncthreads();

    // ---- softmax stats (warp 0) ----
    if (w == 0) {
        float m = -3.0e38f;
        for (int j = lane; j < width; j += 32) m = fmaxf(m, sc[j]);
        #pragma unroll
        for (int off = 16; off > 0; off >>= 1)
            m = fmaxf(m, __shfl_xor_sync(0xffffffffu, m, off));
        float s = 0.f;
        for (int j = lane; j < width; j += 32) s += expf(sc[j] - m);
        #pragma unroll
        for (int off = 16; off > 0; off >>= 1)
            s += __shfl_xor_sync(0xffffffffu, s, off);
        if (lane == 0) { s_max = m; s_sum = s; }
    }
    __syncthreads();

    // ---- at = softmax * gaussian (D*D/2 = 2048) ----
    if (tid < width) {
        float d = (float)(left + tid) - p;
        ats[tid] = expf(sc[tid] - s_max) / s_sum * expf(-d * d * (1.0f / 2048.0f));
    }
    __syncthreads();

    // ---- context: ct[h] = sum_j at[j] * enc[b, left+j, h] ----
    float acc = 0.f;
    const float* col = encb + tid;
    int j = 0;
    for (; j + 4 <= width; j += 4) {
        acc += ats[j]     * col[(size_t)j * HH];
        acc += ats[j + 1] * col[(size_t)(j + 1) * HH];
        acc += ats[j + 2] * col[(size_t)(j + 2) * HH];
        acc += ats[j + 3] * col[(size_t)(j + 3) * HH];
    }
    for (; j < width; j++) acc += ats[j] * col[(size_t)j * HH];
    g_ct[(size_t)b * HH + tid] = acc;
}

// ---------------- deterministic split-K reduce into d_out -------------------
__global__ void reduce_out(float* __restrict__ out)
{
    int idx = blockIdx.x * blockDim.x + threadIdx.x;   // 64*1024
    float s = 0.f;
    #pragma unroll
    for (int k = 0; k < SPLITK_S; k++)
        s += g_part3[(size_t)k * BB * HH + idx];
    out[idx] = s;
}

// ---------------------------------------------------------------------------
extern "C" void kernel_launch(void* const* d_in, const int* in_sizes, int n_in,
                              void* d_out, int out_size)
{
    const float* enc      = (const float*)d_in[0];   // [64, 2048, 1024]
    const float* x_t      = (const float*)d_in[1];   // [64, 2048]
    const float* h0       = (const float*)d_in[2];   // [64, 1024]
    const float* c0       = (const float*)d_in[3];   // [64, 1024]
    const float* W_ih     = (const float*)d_in[4];   // [4096, 2048]
    const float* W_hh     = (const float*)d_in[5];   // [4096, 1024]
    const float* b_ih     = (const float*)d_in[6];   // [4096]
    const float* b_hh     = (const float*)d_in[7];   // [4096]
    const float* W_ht2tan = (const float*)d_in[8];   // [1024, 1024]
    const float* W_tan2pt = (const float*)d_in[9];   // [1, 1024]
    const float* W_ct2ht  = (const float*)d_in[10];  // [1024, 1024]
    const int*   elen     = (const int*)d_in[11];    // [64]
    float* out = (float*)d_out;
    (void)in_sizes; (void)n_in; (void)out_size;

    float *p_gpart, *p_yt, *p_part2, *p_part3, *p_ct;
    cudaGetSymbolAddress((void**)&p_gpart, g_gpart);
    cudaGetSymbolAddress((void**)&p_yt,    g_yt);
    cudaGetSymbolAddress((void**)&p_part2, g_part2);
    cudaGetSymbolAddress((void**)&p_part3, g_part3);
    cudaGetSymbolAddress((void**)&p_ct,    g_ct);

    // 1) gates partials = [x_t|h0] @ [W_ih|W_hh]^T  (N=4096, K=3072, split-K=2)
    gemm_db<<<dim3(G4H / BN, SPLITK_G), 128>>>(x_t, W_ih, 2048, h0, W_hh,
                                               p_gpart, G4H, 3072 / SPLITK_G);
    // 2) gates reduce + bias + LSTM cell -> yt
    lstm_fuse<<<(BB * HH) / 256, 256>>>(c0, b_ih, b_hh);
    // 3) pre-tanh partials = yt @ W_ht2tan^T  (split-K=8)
    gemm_db<<<dim3(HH / BN, SPLITK_S), 128>>>(p_yt, W_ht2tan, HH, nullptr, nullptr,
                                              p_part2, HH, HH / SPLITK_S);
    // 4) fused p_t + windowed attention -> ct
    attn_pt_kernel<<<BB, 1024>>>(enc, W_tan2pt, elen);
    // 5) ht partials = ct @ W_ct2ht^T  (split-K=8)
    gemm_db<<<dim3(HH / BN, SPLITK_S), 128>>>(p_ct, W_ct2ht, HH, nullptr, nullptr,
                                              p_part3, HH, HH / SPLITK_S);
    // 6) reduce partials -> d_out
    reduce_out<<<(BB * HH) / 256, 256>>>(out);
}